// round 14
// baseline (speedup 1.0000x reference)
#include <cuda_runtime.h>

#define BB 4
#define NT 256
#define NZ 384
#define NXX 384
#define NREC 128
#define DTc 0.001f
#define DHc 10.0f

#define NBLK 128
#define BLK_PER_B (NBLK / BB)      // 32 blocks per batch
#define ROWS 12                    // owned rows per block
#define NPAIR (NXX / 2)            // 192 column pairs
#define NGRP 4                     // row groups
#define RPT 3                      // rows per thread
#define NTHR (NPAIR * NGRP)        // 768 threads

// Packed halo word: hi32 = step counter (t+1 when u(t) published), lo32 = value.
__device__ __align__(16) unsigned long long d_pack[2][NBLK][2][NXX];
#define SLOT_OFF (NBLK * 2 * NXX)

__global__ void zero_kernel() {
    const int n = 2 * NBLK * 2 * NXX;
    for (int i = blockIdx.x * blockDim.x + threadIdx.x; i < n;
         i += gridDim.x * blockDim.x)
        ((unsigned long long*)d_pack)[i] = 0ull;
}

__device__ __forceinline__ unsigned long long ld_vol_u64(
        const unsigned long long* p) {
    unsigned long long v;
    asm volatile("ld.volatile.global.u64 %0, [%1];" : "=l"(v) : "l"(p));
    return v;
}
__device__ __forceinline__ void st_vol_u64x2(unsigned long long* p,
                                             unsigned long long a,
                                             unsigned long long b) {
    asm volatile("st.volatile.global.v2.u64 [%0], {%1, %2};"
                 :: "l"(p), "l"(a), "l"(b));
}
__device__ __forceinline__ void ld_vol_u64x2(const unsigned long long* p,
                                             unsigned long long& a,
                                             unsigned long long& b) {
    asm volatile("ld.volatile.global.v2.u64 {%0, %1}, [%2];"
                 : "=l"(a), "=l"(b) : "l"(p));
}

// ---- packed f32x2 helpers ----
#define PACKF(out, lo, hi) \
    asm("mov.b64 %0, {%1, %2};" : "=l"(out) : "f"(lo), "f"(hi))
#define PACKU(out, lo, hi) \
    asm("mov.b64 %0, {%1, %2};" : "=l"(out) : "r"(lo), "r"(hi))
#define UNPACKU(lo, hi, in) \
    asm("mov.b64 {%0, %1}, %2;" : "=r"(lo), "=r"(hi) : "l"(in))
#define ADDX2(d, a, b) \
    asm("add.rn.f32x2 %0, %1, %2;" : "=l"(d) : "l"(a), "l"(b))
#define MULX2(d, a, b) \
    asm("mul.rn.f32x2 %0, %1, %2;" : "=l"(d) : "l"(a), "l"(b))
#define FMAX2(d, a, b, c) \
    asm("fma.rn.f32x2 %0, %1, %2, %3;" : "=l"(d) : "l"(a), "l"(b), "l"(c))

#define C_M4  0xC0800000C0800000ull   // {-4,-4}
#define C_TWO 0x4000000040000000ull   // {2,2}
#define C_M1  0xBF800000BF800000ull   // {-1,-1}

__global__ __launch_bounds__(NTHR, 1) void wave_kernel(
    const float* __restrict__ xsrc,   // [B, NT]
    const float* __restrict__ vp,     // [NZ, NX]
    const int*   __restrict__ src_y,
    const int*   __restrict__ src_x,
    const int*   __restrict__ rec_y,
    const int*   __restrict__ rec_x,
    float*       __restrict__ out)    // [NT, B, NREC]
{
    __shared__ float sb0[ROWS * NXX];
    __shared__ float sb1[ROWS * NXX];
    __shared__ float sxs[NT];

    const int tid = threadIdx.x;
    const int p   = tid % NPAIR;
    const int g   = tid / NPAIR;            // warp-uniform (6 warps/group)
    const int x0  = 2 * p;
    const int x1  = x0 + 1;
    const int blk = blockIdx.x;
    const int b   = blk / BLK_PER_B;
    const int bib = blk % BLK_PER_B;
    const int z0  = bib * ROWS;
    const int rowbase = g * RPT;
    const float inv_dh2 = 1.0f / (DHc * DHc);

    const int topBlk = (bib > 0) ? blk - 1 : -1;
    const int botBlk = (bib < BLK_PER_B - 1) ? blk + 1 : -1;
    const bool isTop = (g == 0);
    const bool isBot = (g == NGRP - 1);
    const int  nb    = isTop ? topBlk : (isBot ? botBlk : -1);
    const bool hasNb = (nb >= 0);
    const int  side  = isTop ? 0 : 1;

    const int sy = src_y[b];
    const int sx = src_x[b];

    unsigned long long ucP[RPT];     // packed {uA,uB} current (u(t-1))
    unsigned long long npvP[RPT];    // packed -u(t-2)
    unsigned long long csP[RPT];     // packed c^2*dt^2/dh^2 (0 at edges)
    unsigned long long srP[RPT];     // packed source-select {0/1}

    for (int i = tid; i < NT; i += NTHR)
        sxs[i] = xsrc[b * NT + i];

#pragma unroll
    for (int k = 0; k < RPT; k++) {
        const int zg = z0 + rowbase + k;
        ucP[k]  = 0ull;
        npvP[k] = 0ull;
        const float cA = vp[zg * NXX + x0] * DTc;
        const float cB = vp[zg * NXX + x1] * DTc;
        const bool zok = (zg > 0 && zg < NZ - 1);
        const float csA = (zok && x0 > 0)       ? (cA * cA * inv_dh2) : 0.0f;
        const float csB = (zok && x1 < NXX - 1) ? (cB * cB * inv_dh2) : 0.0f;
        PACKF(csP[k], csA, csB);
        const float sA = (zg == sy && x0 == sx) ? 1.0f : 0.0f;
        const float sB = (zg == sy && x1 == sx) ? 1.0f : 0.0f;
        PACKF(srP[k], sA, sB);
        sb0[(rowbase + k) * NXX + x0] = 0.0f;
        sb0[(rowbase + k) * NXX + x1] = 0.0f;
        sb1[(rowbase + k) * NXX + x0] = 0.0f;
        sb1[(rowbase + k) * NXX + x1] = 0.0f;
    }

    // receiver gather handled by interior-group threads tid in [192, 320)
    const int rtid = tid - 192;
    int rmine = 0, roff = 0;
    float* outp = out;
    if (rtid >= 0 && rtid < NREC) {
        const int ry = rec_y[rtid];
        const int rx = rec_x[rtid];
        rmine = (ry >= z0 && ry < z0 + ROWS);
        roff  = (ry - z0) * NXX + rx;
        outp  = out + b * NREC + rtid;
    }

    const int pbase = rowbase * NXX + x0;
    const int dxl   = (x0 > 0) ? 1 : 0;
    const int dxr   = (x1 < NXX - 1) ? 1 : 0;
    const int bk    = isTop ? 0 : RPT - 1;

    unsigned long long* pubA = &d_pack[0][blk][side][x0];
    const unsigned long long* polA =
        hasNb ? &d_pack[0][nb][side ^ 1][x0] : pubA;

    unsigned long long hNbP = 0ull;                   // packed neighbor boundary
    unsigned long long specA = 0ull, specB = 0ull;
    const unsigned long long m4 = C_M4, two = C_TWO, m1 = C_M1;

    __syncthreads();

    // packed row update: up/dn packed; left/right via scalar LDS + pack
    #define DO_ROWP(k, upP, dnP, RBUF, WBUF, xtP)                               \
    {                                                                           \
        const int pr = pbase + (k) * NXX;                                       \
        const unsigned long long uP = ucP[k];                                   \
        unsigned loU, hiU; UNPACKU(loU, hiU, uP);                               \
        const float Lv = RBUF[pr - dxl];                                        \
        const float Rv = RBUF[pr + 1 + dxr];                                    \
        unsigned long long lP, rP;                                              \
        asm("mov.b64 %0, {%1, %2};" : "=l"(lP) : "f"(Lv), "r"(loU));            \
        asm("mov.b64 %0, {%1, %2};" : "=l"(rP) : "r"(hiU), "f"(Rv));            \
        unsigned long long s1, s2, s3, lap, term, hn;                           \
        ADDX2(s1, (upP), (dnP));                                                \
        ADDX2(s2, lP, rP);                                                      \
        ADDX2(s3, s1, s2);                                                      \
        FMAX2(lap, uP, m4, s3);                                                 \
        FMAX2(term, uP, two, npvP[k]);                                          \
        FMAX2(hn, csP[k], lap, term);                                           \
        FMAX2(hn, srP[k], (xtP), hn);                                           \
        MULX2(npvP[k], uP, m1);                                                 \
        ucP[k] = hn;                                                            \
        *(unsigned long long*)&WBUF[pr] = hn;                                   \
    }

    #define STEP(T, RBUF, WBUF, SOFF, PSOFF)                                    \
    {                                                                           \
        const int   t  = (T);                                                   \
        const float xt = sxs[t];                                                \
        unsigned long long xtP; PACKF(xtP, xt, xt);                             \
        const unsigned long long o0 = ucP[0], o1 = ucP[1], o2 = ucP[2];         \
        /* Phase 0: consume last step's spec = neighbor u(t-1) */               \
        if (hasNb && t > 0) {                                                   \
            unsigned long long vA = specA, vB = specB;                          \
            while ((int)(vA >> 32) < t) vA = ld_vol_u64(polA + (PSOFF));        \
            while ((int)(vB >> 32) < t) vB = ld_vol_u64(polA + (PSOFF) + 1);    \
            PACKU(hNbP, (unsigned)vA, (unsigned)vB);                            \
        }                                                                       \
        /* Phase 1: boundary row first, publish immediately */                  \
        if (isTop) {                                                            \
            DO_ROWP(0, hNbP, o1, RBUF, WBUF, xtP);                              \
            if (hasNb) {                                                        \
                unsigned vlo, vhi; UNPACKU(vlo, vhi, ucP[0]);                   \
                const unsigned long long hi =                                   \
                    (unsigned long long)(unsigned)(t + 1) << 32;                \
                st_vol_u64x2(pubA + (SOFF), hi | vlo, hi | vhi);                \
            }                                                                   \
        } else if (isBot) {                                                     \
            DO_ROWP(2, o1, hNbP, RBUF, WBUF, xtP);                              \
            if (hasNb) {                                                        \
                unsigned vlo, vhi; UNPACKU(vlo, vhi, ucP[2]);                   \
                const unsigned long long hi =                                   \
                    (unsigned long long)(unsigned)(t + 1) << 32;                \
                st_vol_u64x2(pubA + (SOFF), hi | vlo, hi | vhi);                \
            }                                                                   \
        }                                                                       \
        /* Phase 2: remaining rows */                                           \
        if (isTop) {                                                            \
            DO_ROWP(1, o0, o2, RBUF, WBUF, xtP);                                \
            const unsigned long long dn =                                       \
                *(const unsigned long long*)&RBUF[pbase + RPT * NXX];           \
            DO_ROWP(2, o1, dn, RBUF, WBUF, xtP);                                \
        } else if (isBot) {                                                     \
            const unsigned long long up =                                       \
                *(const unsigned long long*)&RBUF[pbase - NXX];                 \
            DO_ROWP(0, up, o1, RBUF, WBUF, xtP);                                \
            DO_ROWP(1, o0, o2, RBUF, WBUF, xtP);                                \
        } else {                                                                \
            const unsigned long long up =                                       \
                *(const unsigned long long*)&RBUF[pbase - NXX];                 \
            DO_ROWP(0, up, o1, RBUF, WBUF, xtP);                                \
            DO_ROWP(1, o0, o2, RBUF, WBUF, xtP);                                \
            const unsigned long long dn =                                       \
                *(const unsigned long long*)&RBUF[pbase + RPT * NXX];           \
            DO_ROWP(2, o1, dn, RBUF, WBUF, xtP);                                \
        }                                                                       \
        /* receiver gather for step t-1 (interior threads, off critical path)*/ \
        if (t > 0 && rmine) { outp[(t - 1) * (BB * NREC)] = RBUF[roff]; }       \
        /* Phase 3: late poll for neighbor u(t); consumed NEXT step */          \
        if (hasNb && t < NT - 1)                                                \
            ld_vol_u64x2(polA + (SOFF), specA, specB);                          \
        __syncthreads();                                                        \
    }

#pragma unroll 1
    for (int tt = 0; tt < NT; tt += 2) {
        STEP(tt,     sb0, sb1, 0, SLOT_OFF)   // even t: publish slot 0
        STEP(tt + 1, sb1, sb0, SLOT_OFF, 0)   // odd  t: publish slot 1
    }
    #undef STEP
    #undef DO_ROWP

    // final receiver gather for t = NT-1 (last wbuf = sb0 since NT even)
    if (rmine)
        outp[(NT - 1) * (BB * NREC)] = sb0[roff];
}

extern "C" void kernel_launch(void* const* d_in, const int* in_sizes, int n_in,
                              void* d_out, int out_size)
{
    const float* xsrc  = (const float*)d_in[0];
    const float* vp    = (const float*)d_in[1];
    const int*   src_y = (const int*)d_in[2];
    const int*   src_x = (const int*)d_in[3];
    const int*   rec_y = (const int*)d_in[4];
    const int*   rec_x = (const int*)d_in[5];
    float*       out   = (float*)d_out;

    zero_kernel<<<128, 512>>>();
    wave_kernel<<<NBLK, NTHR>>>(xsrc, vp, src_y, src_x, rec_y, rec_x, out);
}